// round 14
// baseline (speedup 1.0000x reference)
#include <cuda_runtime.h>
#include <math.h>

#define NB 8192
#define SPIN 365
#define TRAIN 6000
#define NSTD (TRAIN - SPIN)   // 5635
#define L2E 1.4426950408889634f

#define CHUNK 16
#define NCHUNK (NB / CHUNK)   // 512
#define NCHUNKP (NCHUNK + 1)  // 513: pad for conflict-free SMEM transpose
#define NPASS 2
#define EXPB 32               // expand blocks; grid = 1 + EXPB

// natural-layout carry (coalesced on both sides)
__device__ float g_carry[NB];
__device__ int   g_flag;   // 0 -> 1 by scan block; reset by last expand block
__device__ int   g_done;

__device__ __forceinline__ float ex2f(float x) {
    float r;
    asm("ex2.approx.f32 %0, %1;" : "=f"(r) : "f"(x));
    return r;
}
__device__ __forceinline__ float tanh_approx(float x) {
    float r;
    asm("tanh.approx.f32 %0, %1;" : "=f"(r) : "f"(x));
    return r;
}
__device__ __forceinline__ float fsig(float x) {
    return __fdividef(1.0f, 1.0f + __expf(-x));
}

// ---------------------------------------------------------------------------
// One kernel, 33 blocks x 1024 threads, all co-resident:
//   block 0      : stage x -> 2-pass chunked scan -> g_carry -> flag=1
//   blocks 1-32  : (pre-flag) constants + obs_std + zero cols + u2 prefetch,
//                  SINGLE-THREAD flag poll -> __syncthreads ->
//                  read g_carry, compute + store 13 columns;
//                  last block resets flag for graph replay
// ---------------------------------------------------------------------------
__global__ void __launch_bounds__(1024, 1) mcp_one(
    const float* __restrict__ x,
    const float* __restrict__ y_obs,
    const float* __restrict__ p_mean_p,
    const float* __restrict__ p_std_p,
    const int*   __restrict__ time_lag_p,
    const float* __restrict__ w_r_yom_p,
    const float* __restrict__ w_r_ylm_p,
    const float* __restrict__ w_r_yfm_p,
    const float* __restrict__ w_r_yvm_p,
    const float* __restrict__ b0_yom_p,
    const float* __restrict__ b1_yom_p,
    const float* __restrict__ b2_yom_p,
    const float* __restrict__ b0_ylm_p,
    const float* __restrict__ b1_ylm_p,
    const float* __restrict__ b2_ylm_p,
    const float* __restrict__ w_s_yvm_p,
    const float* __restrict__ b0_yrm_p,
    float* __restrict__ out)
{
    extern __shared__ float sm[];          // scan block only
    __shared__ float redS[32];
    __shared__ float redQ[32];
    __shared__ float s_std_sh;
    __shared__ float s_seed[NCHUNK + 1];

    const int tid = threadIdx.x;
    const int wid = tid >> 5;
    const int lid = tid & 31;

    const float mo = *p_mean_p;
    const float so = *p_std_p;
    int time_lag = *time_lag_p;
    if (time_lag < 0)  time_lag = 0;
    if (time_lag > NB) time_lag = NB;

    const float inv_so = __fdividef(1.0f, so);
    const float Bl = (*b1_ylm_p) * inv_so;
    const float Kl = (*b0_ylm_p) - mo * Bl;
    const float b2l_over_SL = (*b2_ylm_p) * (1.0f / 1.898f);

    if (blockIdx.x == 0) {
        // =========================== SCAN BLOCK ===========================
        float* s_u1 = sm;
        float* s_u2 = sm + CHUNK * NCHUNKP;
        float* s_ag = sm + 2 * CHUNK * NCHUNKP;
        float* s_c  = sm + 3 * CHUNK * NCHUNKP;

        // stage x (coalesced LDG.64, padded STS)
        const float2* x2 = (const float2*)x;
        for (int i = tid; i < NB; i += 1024) {
            int k = i >> 4;
            int j = i & (CHUNK - 1);
            float2 v = x2[i];
            int a = j * NCHUNKP + k;
            s_u1[a] = v.x;
            s_u2[a] = v.y;
            s_ag[a] = -L2E * (Kl + (v.y - 2.9086f) * b2l_over_SL);
        }
        __syncthreads();

        if (wid < 16) {
            const float eo    = __expf(*w_r_yom_p);
            const float el    = __expf(*w_r_ylm_p);
            const float ef    = __expf(*w_r_yfm_p);
            const float denom = eo + el + ef;
            const float co    = __fdividef(eo, denom);
            const float cl    = __fdividef(el, denom);

            const float Bo  = (*b1_yom_p) * inv_so;
            const float Ko  = (*b0_yom_p) - mo * Bo - mo * inv_so * (*b2_yom_p);
            const float Bo2 = -L2E * Bo;
            const float Ko2 = -L2E * Ko;
            const float Bl2 = -L2E * Bl;

            const float sv  = fsig(*w_r_yvm_p);
            const float es  = __expf(*w_s_yvm_p);
            const float ebr = __expf(*b0_yrm_p);
            const float thresh = ebr * 500.0f;
            const float Ct = es * (1.0f / 500.0f);
            const float Dt = ebr * es;

            const int k     = tid;          // chunk id, 0..511
            const int begin = k * CHUNK;

            #pragma unroll
            for (int pass = 0; pass < NPASS; ++pass) {
                const bool last = (pass == NPASS - 1);
                float c = (pass == 0 || k == 0) ? 0.0f : s_seed[k];

                #pragma unroll
                for (int j = 0; j < CHUNK; ++j) {
                    const int i = begin + j;
                    float u2 = s_u2[j * NCHUNKP + k];
                    float ag = s_ag[j * NCHUNKP + k];

                    float exo = ex2f(fmaf(c, Bo2, Ko2));
                    float exl = ex2f(fmaf(c, Bl2, ag));
                    float rc  = __fdividef(u2, c);
                    float th  = tanh_approx(fmaf(c, Ct, -Dt));

                    float oo  = co * __fdividef(1.0f, 1.0f + exo);
                    float ol  = cl * __fdividef(1.0f, 1.0f + exl);
                    float olc = (c > 0.0f) ? fminf(ol, rc) : ol;
                    float f   = 1.0f - (oo + olc);
                    float ov  = fminf(sv * th, f);
                    float mr  = ov * fabsf(c - thresh);
                    float c1  = fmaf(f, c, s_u1[j * NCHUNKP + k]) - mr;

                    if (last) s_c[j * NCHUNKP + k] = c;
                    if (i >= time_lag) c = c1;
                }
                if (!last) {
                    s_seed[k + 1] = c;
                    asm volatile("bar.sync 2, 512;" ::: "memory");
                }
            }
        }
        __syncthreads();

        // coalesced natural-layout carry writeback
        for (int i = tid; i < NB; i += 1024) {
            g_carry[i] = s_c[(i & (CHUNK - 1)) * NCHUNKP + (i >> 4)];
        }
        __threadfence();
        __syncthreads();
        if (tid == 0) atomicExch(&g_flag, 1);   // release
        return;
    }

    // ============================ EXPAND BLOCKS ============================
    // ---- pre-flag work (overlapped with the scan) ----

    const float eo    = __expf(*w_r_yom_p);
    const float el    = __expf(*w_r_ylm_p);
    const float ef    = __expf(*w_r_yfm_p);
    const float denom = eo + el + ef;
    const float co    = __fdividef(eo, denom);
    const float cl    = __fdividef(el, denom);

    const float Bo = (*b1_yom_p) * inv_so;
    const float Ko = (*b0_yom_p) - mo * Bo - mo * inv_so * (*b2_yom_p);

    const float sv  = fsig(*w_r_yvm_p);
    const float es  = __expf(*w_s_yvm_p);
    const float ebr = __expf(*b0_yrm_p);
    const float thresh = ebr * 500.0f;
    const float Ct2 = es * (2.0f / 500.0f);
    const float Dt2 = 2.0f * ebr * es;
    const float sv2 = 2.0f * sv;

    // obs_std (redundant per block; deterministic identical result)
    {
        float s = 0.0f, q = 0.0f;
        for (int i = SPIN + tid; i < TRAIN; i += 1024) {
            float v = y_obs[i];
            s += v;
            q = fmaf(v, v, q);
        }
        #pragma unroll
        for (int off = 16; off > 0; off >>= 1) {
            s += __shfl_down_sync(0xFFFFFFFFu, s, off);
            q += __shfl_down_sync(0xFFFFFFFFu, q, off);
        }
        if (lid == 0) { redS[wid] = s; redQ[wid] = q; }
        __syncthreads();
        if (tid == 0) {
            float S = 0.0f, Q = 0.0f;
            #pragma unroll
            for (int w = 0; w < 32; ++w) { S += redS[w]; Q += redQ[w]; }
            const float n = (float)NSTD;
            float var = (Q - __fdividef(S * S, n)) * __fdividef(1.0f, n - 1.0f);
            s_std_sh = sqrtf(var);
        }
        __syncthreads();
    }
    const float obsstd = s_std_sh;

    const int i = (blockIdx.x - 1) * 256 + tid;
    const bool active = (tid < 256);

    float u2 = 0.0f;
    if (active) {
        u2 = x[2 * i + 1];                 // prefetch
        out[4 * NB + i] = 0.0f;            // bp_n    (always 0)
        out[5 * NB + i] = 0.0f;            // Gate_ib (always 0)
    }

    // ---- wait for carry: SINGLE thread polls, block released by bar ----
    if (tid == 0) {
        volatile int* fp = &g_flag;
        while (*fp == 0) { __nanosleep(32); }
        __threadfence();                   // acquire
    }
    __syncthreads();

    if (active) {
        if (i < time_lag) {
            out[0 * NB + i] = 0.0f;
            out[1 * NB + i] = 0.0f;
            out[2 * NB + i] = 0.0f;
            out[3 * NB + i] = 0.0f;
            out[6 * NB + i] = 0.0f;
            out[7 * NB + i] = 0.0f;
            out[8 * NB + i] = 0.0f;
            out[9 * NB + i] = 0.0f;
            out[10 * NB + 2 * i]     = 0.0f;
            out[10 * NB + 2 * i + 1] = 0.0f;
            out[12 * NB + i] = 0.0f;
            out[13 * NB + i] = 0.0f;
            out[14 * NB + i] = 0.0f;
        } else {
            const float c = g_carry[i];
            const float argl = Kl + (u2 - 2.9086f) * b2l_over_SL;

            float oo  = co * fsig(fmaf(c, Bo, Ko));
            float ol  = cl * fsig(fmaf(c, Bl, argl));
            float rc  = __fdividef(u2, c);
            float olc = (c > 0.0f) ? fminf(ol, rc) : ol;
            float f   = (1.0f - oo) - olc;
            float e2t = __expf(fmaf(c, Ct2, -Dt2));
            float ov1 = sv - __fdividef(sv2, e2t + 1.0f);   // sv * tanh (accurate)
            float ov  = fminf(ov1, f);
            float mr  = ov * fabsf(c - thresh);
            float h   = oo * c;

            out[0 * NB + i] = h;
            out[1 * NB + i] = c;
            out[2 * NB + i] = ol * c;
            out[3 * NB + i] = olc * c;
            out[6 * NB + i] = oo;
            out[7 * NB + i] = ol;
            out[8 * NB + i] = olc;
            out[9 * NB + i] = f;
            out[10 * NB + 2 * i]     = h;
            out[10 * NB + 2 * i + 1] = obsstd;
            out[12 * NB + i] = obsstd;
            out[13 * NB + i] = ov;
            out[14 * NB + i] = mr;
        }
    }

    // ---- reset protocol for graph replay ----
    __threadfence();
    __syncthreads();
    if (tid == 0) {
        int old = atomicAdd(&g_done, 1);
        if (old == EXPB - 1) {        // last expand block: everyone is past the spin
            g_done = 0;
            atomicExch(&g_flag, 0);
        }
    }
}

extern "C" void kernel_launch(void* const* d_in, const int* in_sizes, int n_in,
                              void* d_out, int out_size)
{
    const float* x        = (const float*)d_in[0];
    const float* y_obs    = (const float*)d_in[1];
    const float* p_mean   = (const float*)d_in[2];
    const float* p_std    = (const float*)d_in[3];
    const int*   time_lag = (const int*)  d_in[5];
    const float* w_r_yom  = (const float*)d_in[6];
    const float* w_r_ylm  = (const float*)d_in[7];
    const float* w_r_yfm  = (const float*)d_in[8];
    const float* w_r_yvm  = (const float*)d_in[9];
    const float* b0_yom   = (const float*)d_in[10];
    const float* b1_yom   = (const float*)d_in[11];
    const float* b2_yom   = (const float*)d_in[12];
    const float* b0_ylm   = (const float*)d_in[13];
    const float* b1_ylm   = (const float*)d_in[14];
    const float* b2_ylm   = (const float*)d_in[15];
    const float* w_s_yvm  = (const float*)d_in[16];
    const float* b0_yrm   = (const float*)d_in[17];

    float* out = (float*)d_out;

    size_t smem = 4 * CHUNK * NCHUNKP * sizeof(float);   // ~128.3 KB dynamic
    cudaFuncSetAttribute(mcp_one,
                         cudaFuncAttributeMaxDynamicSharedMemorySize, (int)smem);

    mcp_one<<<1 + EXPB, 1024, smem>>>(
        x, y_obs, p_mean, p_std, time_lag,
        w_r_yom, w_r_ylm, w_r_yfm, w_r_yvm,
        b0_yom, b1_yom, b2_yom,
        b0_ylm, b1_ylm, b2_ylm,
        w_s_yvm, b0_yrm, out);
}

// round 15
// speedup vs baseline: 1.1376x; 1.1376x over previous
#include <cuda_runtime.h>
#include <math.h>

#define NB 8192
#define SPIN 365
#define TRAIN 6000
#define NSTD (TRAIN - SPIN)   // 5635
#define L2E 1.4426950408889634f

#define CHUNK 16
#define NCHUNK (NB / CHUNK)   // 512
#define NCHUNKP (NCHUNK + 1)  // 513: pad for conflict-free SMEM transpose
#define NPASS 2
#define NBLK 8                // each block: full redundant scan + 1/8 expand

__device__ __forceinline__ float ex2f(float x) {
    float r;
    asm("ex2.approx.f32 %0, %1;" : "=f"(r) : "f"(x));
    return r;
}
__device__ __forceinline__ float tanh_approx(float x) {
    float r;
    asm("tanh.approx.f32 %0, %1;" : "=f"(r) : "f"(x));
    return r;
}
__device__ __forceinline__ float fsig(float x) {
    return __fdividef(1.0f, 1.0f + __expf(-x));
}

// ---------------------------------------------------------------------------
// ONE kernel, 8 blocks x 1024 threads. Every block independently:
//   phase 0: stages x into padded-transposed SMEM
//   phase 1: warps 0-15 run the full 2-pass chunked scan (carry -> SMEM);
//            warps 16-31 compute obs_std (FP32) concurrently
//   phase 2: expands its own 1024-element slice of all 15 output columns
// Redundant scans are deterministic (identical FP ops) -> identical carries.
// No inter-block communication, no flags, no second launch.
// ---------------------------------------------------------------------------
__global__ void __launch_bounds__(1024, 1) mcp_all(
    const float* __restrict__ x,
    const float* __restrict__ y_obs,
    const float* __restrict__ p_mean_p,
    const float* __restrict__ p_std_p,
    const int*   __restrict__ time_lag_p,
    const float* __restrict__ w_r_yom_p,
    const float* __restrict__ w_r_ylm_p,
    const float* __restrict__ w_r_yfm_p,
    const float* __restrict__ w_r_yvm_p,
    const float* __restrict__ b0_yom_p,
    const float* __restrict__ b1_yom_p,
    const float* __restrict__ b2_yom_p,
    const float* __restrict__ b0_ylm_p,
    const float* __restrict__ b1_ylm_p,
    const float* __restrict__ b2_ylm_p,
    const float* __restrict__ w_s_yvm_p,
    const float* __restrict__ b0_yrm_p,
    float* __restrict__ out)
{
    // padded transposed layout: (chunk k, pos j) lives at [j*NCHUNKP + k]
    extern __shared__ float sm[];
    float* s_u1 = sm;                        // [CHUNK][NCHUNKP]
    float* s_u2 = sm + CHUNK * NCHUNKP;      // [CHUNK][NCHUNKP]
    float* s_ag = sm + 2 * CHUNK * NCHUNKP;  // [CHUNK][NCHUNKP]
    float* s_c  = sm + 3 * CHUNK * NCHUNKP;  // [CHUNK][NCHUNKP] carry

    __shared__ float s_seed[NCHUNK + 1];
    __shared__ float redS[16];
    __shared__ float redQ[16];
    __shared__ float s_std;

    const int tid = threadIdx.x;
    const int wid = tid >> 5;
    const int lid = tid & 31;

    const float mo = *p_mean_p;
    const float so = *p_std_p;
    int time_lag = *time_lag_p;
    if (time_lag < 0)  time_lag = 0;
    if (time_lag > NB) time_lag = NB;

    // ---- derived constants (every thread; needed by scan and expand)
    const float inv_so = __fdividef(1.0f, so);
    const float Bl = (*b1_ylm_p) * inv_so;
    const float Kl = (*b0_ylm_p) - mo * Bl;
    const float b2l_over_SL = (*b2_ylm_p) * (1.0f / 1.898f);

    const float eo    = __expf(*w_r_yom_p);
    const float el    = __expf(*w_r_ylm_p);
    const float ef    = __expf(*w_r_yfm_p);
    const float denom = eo + el + ef;
    const float co    = __fdividef(eo, denom);
    const float cl    = __fdividef(el, denom);

    const float Bo  = (*b1_yom_p) * inv_so;
    const float Ko  = (*b0_yom_p) - mo * Bo - mo * inv_so * (*b2_yom_p);
    const float Bo2 = -L2E * Bo;
    const float Ko2 = -L2E * Ko;
    const float Bl2 = -L2E * Bl;

    const float sv  = fsig(*w_r_yvm_p);
    const float es  = __expf(*w_s_yvm_p);
    const float ebr = __expf(*b0_yrm_p);
    const float thresh = ebr * 500.0f;
    const float Ct  = es * (1.0f / 500.0f);
    const float Dt  = ebr * es;
    const float Ct2 = es * (2.0f / 500.0f);
    const float Dt2 = 2.0f * ebr * es;
    const float sv2 = 2.0f * sv;

    // ---- phase 0: stage x (coalesced LDG.64, conflict-free padded STS)
    const float2* x2 = (const float2*)x;
    for (int i = tid; i < NB; i += 1024) {
        int k = i >> 4;
        int j = i & (CHUNK - 1);
        float2 v = x2[i];
        int a = j * NCHUNKP + k;
        s_u1[a] = v.x;
        s_u2[a] = v.y;
        s_ag[a] = -L2E * (Kl + (v.y - 2.9086f) * b2l_over_SL);
    }
    __syncthreads();

    // ---- phase 1: warps 0-15 scan; warps 16-31 obs_std
    if (wid < 16) {
        const int k     = tid;          // chunk id, 0..511
        const int begin = k * CHUNK;

        #pragma unroll
        for (int pass = 0; pass < NPASS; ++pass) {
            const bool last = (pass == NPASS - 1);
            float c = (pass == 0 || k == 0) ? 0.0f : s_seed[k];

            #pragma unroll
            for (int j = 0; j < CHUNK; ++j) {
                const int i = begin + j;
                float u2 = s_u2[j * NCHUNKP + k];
                float ag = s_ag[j * NCHUNKP + k];

                float exo = ex2f(fmaf(c, Bo2, Ko2));        // e^{-xo}
                float exl = ex2f(fmaf(c, Bl2, ag));         // e^{-xl}
                float rc  = __fdividef(u2, c);
                float th  = tanh_approx(fmaf(c, Ct, -Dt));

                float oo  = co * __fdividef(1.0f, 1.0f + exo);
                float ol  = cl * __fdividef(1.0f, 1.0f + exl);
                float olc = (c > 0.0f) ? fminf(ol, rc) : ol;
                float f   = 1.0f - (oo + olc);
                float ov  = fminf(sv * th, f);
                float mr  = ov * fabsf(c - thresh);
                float c1  = fmaf(f, c, s_u1[j * NCHUNKP + k]) - mr;

                if (last) s_c[j * NCHUNKP + k] = c;   // pre-update carry
                if (i >= time_lag) c = c1;
            }
            if (!last) {
                s_seed[k + 1] = c;
                asm volatile("bar.sync 2, 512;" ::: "memory");
            }
        }
    } else {
        // obs_std (warps 16-31), all FP32
        float s = 0.0f, q = 0.0f;
        for (int i = SPIN + (tid - 512); i < TRAIN; i += 512) {
            float v = y_obs[i];
            s += v;
            q = fmaf(v, v, q);
        }
        #pragma unroll
        for (int off = 16; off > 0; off >>= 1) {
            s += __shfl_down_sync(0xFFFFFFFFu, s, off);
            q += __shfl_down_sync(0xFFFFFFFFu, q, off);
        }
        if (lid == 0) { redS[wid - 16] = s; redQ[wid - 16] = q; }
        asm volatile("bar.sync 1, 512;" ::: "memory");
        if (wid == 16 && lid == 0) {
            float S = 0.0f, Q = 0.0f;
            #pragma unroll
            for (int w = 0; w < 16; ++w) { S += redS[w]; Q += redQ[w]; }
            const float n = (float)NSTD;
            float var = (Q - __fdividef(S * S, n)) * __fdividef(1.0f, n - 1.0f);
            s_std = sqrtf(var);
        }
    }
    __syncthreads();   // carry + obs_std ready (block-local)

    // ---- phase 2: expand this block's 1024-element slice
    const float obsstd = s_std;
    const int i = blockIdx.x * 1024 + tid;

    if (i < time_lag) {
        out[0 * NB + i] = 0.0f;
        out[1 * NB + i] = 0.0f;
        out[2 * NB + i] = 0.0f;
        out[3 * NB + i] = 0.0f;
        out[4 * NB + i] = 0.0f;
        out[5 * NB + i] = 0.0f;
        out[6 * NB + i] = 0.0f;
        out[7 * NB + i] = 0.0f;
        out[8 * NB + i] = 0.0f;
        out[9 * NB + i] = 0.0f;
        out[10 * NB + 2 * i]     = 0.0f;
        out[10 * NB + 2 * i + 1] = 0.0f;
        out[12 * NB + i] = 0.0f;
        out[13 * NB + i] = 0.0f;
        out[14 * NB + i] = 0.0f;
        return;
    }

    const int j = i & (CHUNK - 1);
    const int k = i >> 4;
    const int a = j * NCHUNKP + k;         // <=2-way LDS conflict, negligible
    const float c  = s_c[a];
    const float u2 = s_u2[a];
    const float argl = Kl + (u2 - 2.9086f) * b2l_over_SL;

    float oo  = co * fsig(fmaf(c, Bo, Ko));
    float ol  = cl * fsig(fmaf(c, Bl, argl));
    float rc  = __fdividef(u2, c);
    float olc = (c > 0.0f) ? fminf(ol, rc) : ol;
    float f   = (1.0f - oo) - olc;
    float e2t = __expf(fmaf(c, Ct2, -Dt2));
    float ov1 = sv - __fdividef(sv2, e2t + 1.0f);   // sv * tanh (accurate)
    float ov  = fminf(ov1, f);
    float mr  = ov * fabsf(c - thresh);
    float h   = oo * c;

    out[0 * NB + i] = h;           // h_n
    out[1 * NB + i] = c;           // c_n
    out[2 * NB + i] = ol * c;      // l_n
    out[3 * NB + i] = olc * c;     // lc_n
    out[4 * NB + i] = 0.0f;        // bp_n
    out[5 * NB + i] = 0.0f;        // Gate_ib
    out[6 * NB + i] = oo;          // Gate_oo
    out[7 * NB + i] = ol;          // Gate_ol
    out[8 * NB + i] = olc;         // Gate_olc
    out[9 * NB + i] = f;           // Gate_f
    out[10 * NB + 2 * i]     = h;        // h_nout[:,0]
    out[10 * NB + 2 * i + 1] = obsstd;   // h_nout[:,1]
    out[12 * NB + i] = obsstd;     // obs_std
    out[13 * NB + i] = ov;         // Gate_ov
    out[14 * NB + i] = mr;         // mr_n
}

extern "C" void kernel_launch(void* const* d_in, const int* in_sizes, int n_in,
                              void* d_out, int out_size)
{
    const float* x        = (const float*)d_in[0];
    const float* y_obs    = (const float*)d_in[1];
    const float* p_mean   = (const float*)d_in[2];
    const float* p_std    = (const float*)d_in[3];
    const int*   time_lag = (const int*)  d_in[5];
    const float* w_r_yom  = (const float*)d_in[6];
    const float* w_r_ylm  = (const float*)d_in[7];
    const float* w_r_yfm  = (const float*)d_in[8];
    const float* w_r_yvm  = (const float*)d_in[9];
    const float* b0_yom   = (const float*)d_in[10];
    const float* b1_yom   = (const float*)d_in[11];
    const float* b2_yom   = (const float*)d_in[12];
    const float* b0_ylm   = (const float*)d_in[13];
    const float* b1_ylm   = (const float*)d_in[14];
    const float* b2_ylm   = (const float*)d_in[15];
    const float* w_s_yvm  = (const float*)d_in[16];
    const float* b0_yrm   = (const float*)d_in[17];

    float* out = (float*)d_out;

    size_t smem = 4 * CHUNK * NCHUNKP * sizeof(float);   // ~128.3 KB dynamic
    cudaFuncSetAttribute(mcp_all,
                         cudaFuncAttributeMaxDynamicSharedMemorySize, (int)smem);

    mcp_all<<<NBLK, 1024, smem>>>(
        x, y_obs, p_mean, p_std, time_lag,
        w_r_yom, w_r_ylm, w_r_yfm, w_r_yvm,
        b0_yom, b1_yom, b2_yom,
        b0_ylm, b1_ylm, b2_ylm,
        w_s_yvm, b0_yrm, out);
}

// round 16
// speedup vs baseline: 1.6536x; 1.4536x over previous
#include <cuda_runtime.h>
#include <math.h>

#define NB 8192
#define SPIN 365
#define TRAIN 6000
#define NSTD (TRAIN - SPIN)   // 5635
#define L2E 1.4426950408889634f

#define CH 16                 // chunk length (proven-exact history = 16)
#define W  16                 // warmup steps per window
#define NBLK 32
#define TPB 256
#define SLICE (NB / NBLK)     // 256
#define NCH (SLICE / CH)      // 16 scan lanes per block
#define NE (SLICE + W)        // 272 staged elements per block
#define NCP 18                // padded k-stride (k = 0..16, pad to 18)

__device__ __forceinline__ float ex2f(float x) {
    float r;
    asm("ex2.approx.f32 %0, %1;" : "=f"(r) : "f"(x));
    return r;
}
__device__ __forceinline__ float tanh_approx(float x) {
    float r;
    asm("tanh.approx.f32 %0, %1;" : "=f"(r) : "f"(x));
    return r;
}
__device__ __forceinline__ float fsig(float x) {
    return __fdividef(1.0f, 1.0f + __expf(-x));
}

// ---------------------------------------------------------------------------
// ONE kernel, 32 blocks x 256 threads. Block b independently:
//   stage x[b*256-16 .. b*256+256) into padded SMEM (zeros below 0)
//   warp 0 lanes 0-15: each scans 32 sequential steps from seed 0 starting
//     16 before its 16-element chunk (bit-identical to the 2-pass global
//     chunked scan with CHUNK=16), storing the last 16 pre-update carries
//   warps 1-7: obs_std (FP32) concurrently
//   all 256 threads: expand one output element each (15 coalesced stores)
// ---------------------------------------------------------------------------
__global__ void __launch_bounds__(TPB, 1) mcp_win(
    const float* __restrict__ x,
    const float* __restrict__ y_obs,
    const float* __restrict__ p_mean_p,
    const float* __restrict__ p_std_p,
    const int*   __restrict__ time_lag_p,
    const float* __restrict__ w_r_yom_p,
    const float* __restrict__ w_r_ylm_p,
    const float* __restrict__ w_r_yfm_p,
    const float* __restrict__ w_r_yvm_p,
    const float* __restrict__ b0_yom_p,
    const float* __restrict__ b1_yom_p,
    const float* __restrict__ b2_yom_p,
    const float* __restrict__ b0_ylm_p,
    const float* __restrict__ b1_ylm_p,
    const float* __restrict__ b2_ylm_p,
    const float* __restrict__ w_s_yvm_p,
    const float* __restrict__ b0_yrm_p,
    float* __restrict__ out)
{
    // padded layout: local element e (0..271): k_e = e>>4, j = e&15
    // addr = j*NCP + k_e  -> conflict-free for staging, scan, and expand
    __shared__ float s_u1[16 * NCP];
    __shared__ float s_u2[16 * NCP];
    __shared__ float s_ag[16 * NCP];
    __shared__ float s_c [16 * NCP];
    __shared__ float redS[7];
    __shared__ float redQ[7];

    const int tid = threadIdx.x;
    const int wid = tid >> 5;
    const int lid = tid & 31;
    const int bstart = blockIdx.x * SLICE;

    const float mo = *p_mean_p;
    const float so = *p_std_p;
    int time_lag = *time_lag_p;
    if (time_lag < 0)  time_lag = 0;
    if (time_lag > NB) time_lag = NB;

    // ---- derived constants (all threads; needed by scan and expand)
    const float inv_so = __fdividef(1.0f, so);
    const float Bl = (*b1_ylm_p) * inv_so;
    const float Kl = (*b0_ylm_p) - mo * Bl;
    const float b2l_over_SL = (*b2_ylm_p) * (1.0f / 1.898f);

    const float eo    = __expf(*w_r_yom_p);
    const float el    = __expf(*w_r_ylm_p);
    const float ef    = __expf(*w_r_yfm_p);
    const float denom = eo + el + ef;
    const float co    = __fdividef(eo, denom);
    const float cl    = __fdividef(el, denom);

    const float Bo  = (*b1_yom_p) * inv_so;
    const float Ko  = (*b0_yom_p) - mo * Bo - mo * inv_so * (*b2_yom_p);
    const float Bo2 = -L2E * Bo;
    const float Ko2 = -L2E * Ko;
    const float Bl2 = -L2E * Bl;

    const float sv  = fsig(*w_r_yvm_p);
    const float es  = __expf(*w_s_yvm_p);
    const float ebr = __expf(*b0_yrm_p);
    const float thresh = ebr * 500.0f;
    const float Ct  = es * (1.0f / 500.0f);
    const float Dt  = ebr * es;
    const float Ct2 = es * (2.0f / 500.0f);
    const float Dt2 = 2.0f * ebr * es;
    const float sv2 = 2.0f * sv;

    // ---- stage the window (272 elements; zeros for global index < 0)
    const float2* x2 = (const float2*)x;
    for (int e = tid; e < NE; e += TPB) {
        int gi = bstart - W + e;
        float2 v = (gi >= 0) ? x2[gi] : make_float2(0.0f, 0.0f);
        int a = (e & 15) * NCP + (e >> 4);
        s_u1[a] = v.x;
        s_u2[a] = v.y;
        s_ag[a] = -L2E * (Kl + (v.y - 2.9086f) * b2l_over_SL);
    }
    __syncthreads();

    if (tid < NCH) {
        // ---- windowed scan: lane k covers slice chunk k with 16-step warmup
        const int k   = tid;
        const int gi0 = bstart + k * CH - W;   // window start (global)
        float c = 0.0f;

        #pragma unroll
        for (int t = 0; t < W + CH; ++t) {
            const int a = (t & 15) * NCP + (k + (t >> 4));
            float u2 = s_u2[a];
            float ag = s_ag[a];

            float exo = ex2f(fmaf(c, Bo2, Ko2));        // e^{-xo}
            float exl = ex2f(fmaf(c, Bl2, ag));         // e^{-xl}
            float rc  = __fdividef(u2, c);
            float th  = tanh_approx(fmaf(c, Ct, -Dt));

            float oo  = co * __fdividef(1.0f, 1.0f + exo);
            float ol  = cl * __fdividef(1.0f, 1.0f + exl);
            float olc = (c > 0.0f) ? fminf(ol, rc) : ol;
            float f   = 1.0f - (oo + olc);
            float ov  = fminf(sv * th, f);
            float mr  = ov * fabsf(c - thresh);
            float c1  = fmaf(f, c, s_u1[a]) - mr;

            if (t >= W) s_c[a] = c;              // pre-update carry
            if (gi0 + t >= time_lag) c = c1;     // masked prefix: no update
        }
    } else if (tid >= 32) {
        // ---- obs_std partials (warps 1-7), FP32
        float s = 0.0f, q = 0.0f;
        for (int i = SPIN + (tid - 32); i < TRAIN; i += TPB - 32) {
            float v = y_obs[i];
            s += v;
            q = fmaf(v, v, q);
        }
        #pragma unroll
        for (int off = 16; off > 0; off >>= 1) {
            s += __shfl_down_sync(0xFFFFFFFFu, s, off);
            q += __shfl_down_sync(0xFFFFFFFFu, q, off);
        }
        if (lid == 0) { redS[wid - 1] = s; redQ[wid - 1] = q; }
    }
    __syncthreads();

    // ---- obs_std finish (every thread; deterministic identical value)
    float S = 0.0f, Q = 0.0f;
    #pragma unroll
    for (int w = 0; w < 7; ++w) { S += redS[w]; Q += redQ[w]; }
    const float nn = (float)NSTD;
    const float obsstd = sqrtf((Q - __fdividef(S * S, nn)) *
                               __fdividef(1.0f, nn - 1.0f));

    // ---- expand: one output element per thread
    const int i = bstart + tid;

    if (i < time_lag) {
        out[0 * NB + i] = 0.0f;
        out[1 * NB + i] = 0.0f;
        out[2 * NB + i] = 0.0f;
        out[3 * NB + i] = 0.0f;
        out[4 * NB + i] = 0.0f;
        out[5 * NB + i] = 0.0f;
        out[6 * NB + i] = 0.0f;
        out[7 * NB + i] = 0.0f;
        out[8 * NB + i] = 0.0f;
        out[9 * NB + i] = 0.0f;
        out[10 * NB + 2 * i]     = 0.0f;
        out[10 * NB + 2 * i + 1] = 0.0f;
        out[12 * NB + i] = 0.0f;
        out[13 * NB + i] = 0.0f;
        out[14 * NB + i] = 0.0f;
        return;
    }

    const int e = tid + W;                       // local element of i
    const int a = (e & 15) * NCP + (e >> 4);
    const float c  = s_c[a];
    const float u2 = s_u2[a];
    const float argl = Kl + (u2 - 2.9086f) * b2l_over_SL;

    float oo  = co * fsig(fmaf(c, Bo, Ko));
    float ol  = cl * fsig(fmaf(c, Bl, argl));
    float rc  = __fdividef(u2, c);
    float olc = (c > 0.0f) ? fminf(ol, rc) : ol;
    float f   = (1.0f - oo) - olc;
    float e2t = __expf(fmaf(c, Ct2, -Dt2));
    float ov1 = sv - __fdividef(sv2, e2t + 1.0f);   // sv * tanh (accurate)
    float ov  = fminf(ov1, f);
    float mr  = ov * fabsf(c - thresh);
    float h   = oo * c;

    out[0 * NB + i] = h;           // h_n
    out[1 * NB + i] = c;           // c_n
    out[2 * NB + i] = ol * c;      // l_n
    out[3 * NB + i] = olc * c;     // lc_n
    out[4 * NB + i] = 0.0f;        // bp_n
    out[5 * NB + i] = 0.0f;        // Gate_ib
    out[6 * NB + i] = oo;          // Gate_oo
    out[7 * NB + i] = ol;          // Gate_ol
    out[8 * NB + i] = olc;         // Gate_olc
    out[9 * NB + i] = f;           // Gate_f
    out[10 * NB + 2 * i]     = h;        // h_nout[:,0]
    out[10 * NB + 2 * i + 1] = obsstd;   // h_nout[:,1]
    out[12 * NB + i] = obsstd;     // obs_std
    out[13 * NB + i] = ov;         // Gate_ov
    out[14 * NB + i] = mr;         // mr_n
}

extern "C" void kernel_launch(void* const* d_in, const int* in_sizes, int n_in,
                              void* d_out, int out_size)
{
    const float* x        = (const float*)d_in[0];
    const float* y_obs    = (const float*)d_in[1];
    const float* p_mean   = (const float*)d_in[2];
    const float* p_std    = (const float*)d_in[3];
    const int*   time_lag = (const int*)  d_in[5];
    const float* w_r_yom  = (const float*)d_in[6];
    const float* w_r_ylm  = (const float*)d_in[7];
    const float* w_r_yfm  = (const float*)d_in[8];
    const float* w_r_yvm  = (const float*)d_in[9];
    const float* b0_yom   = (const float*)d_in[10];
    const float* b1_yom   = (const float*)d_in[11];
    const float* b2_yom   = (const float*)d_in[12];
    const float* b0_ylm   = (const float*)d_in[13];
    const float* b1_ylm   = (const float*)d_in[14];
    const float* b2_ylm   = (const float*)d_in[15];
    const float* w_s_yvm  = (const float*)d_in[16];
    const float* b0_yrm   = (const float*)d_in[17];

    float* out = (float*)d_out;

    mcp_win<<<NBLK, TPB>>>(
        x, y_obs, p_mean, p_std, time_lag,
        w_r_yom, w_r_ylm, w_r_yfm, w_r_yvm,
        b0_yom, b1_yom, b2_yom,
        b0_ylm, b1_ylm, b2_ylm,
        w_s_yvm, b0_yrm, out);
}

// round 17
// speedup vs baseline: 1.9292x; 1.1667x over previous
#include <cuda_runtime.h>
#include <math.h>

#define NB 8192
#define SPIN 365
#define TRAIN 6000
#define NSTD (TRAIN - SPIN)   // 5635
#define L2E 1.4426950408889634f

#define CH 8                  // chunk length per scan lane
#define W  12                 // warmup steps (min history; see accuracy ledger)
#define NBLK 32
#define TPB 256
#define SLICE (NB / NBLK)     // 256
#define NCH (SLICE / CH)      // 32 scan lanes = warp 0
#define NE (SLICE + W)        // 268 staged elements per block
#define NCP 35                // padded stride for (l>>3) index (0..33 -> pad 35)

__device__ __forceinline__ float ex2f(float x) {
    float r;
    asm("ex2.approx.f32 %0, %1;" : "=f"(r) : "f"(x));
    return r;
}
__device__ __forceinline__ float tanh_approx(float x) {
    float r;
    asm("tanh.approx.f32 %0, %1;" : "=f"(r) : "f"(x));
    return r;
}
__device__ __forceinline__ float fsig(float x) {
    return __fdividef(1.0f, 1.0f + __expf(-x));
}

// ---------------------------------------------------------------------------
// ONE kernel, 32 blocks x 256 threads. Block b independently:
//   stage x[b*256-12 .. b*256+256) into padded SMEM (zeros below 0)
//   warp 0 (32 lanes): lane k scans 20 sequential steps from seed 0 starting
//     12 before its 8-element chunk; stores the last 8 pre-update carries
//   warps 1-7: obs_std (FP32) concurrently
//   all 256 threads: expand one output element each (15 coalesced stores)
// Local element l = 8k + t; SMEM addr = (l&7)*NCP + (l>>3):
//   scan step t: addr = (t&7)*NCP + k + (t>>3) -> consecutive k = distinct banks
// ---------------------------------------------------------------------------
__global__ void __launch_bounds__(TPB, 1) mcp_win(
    const float* __restrict__ x,
    const float* __restrict__ y_obs,
    const float* __restrict__ p_mean_p,
    const float* __restrict__ p_std_p,
    const int*   __restrict__ time_lag_p,
    const float* __restrict__ w_r_yom_p,
    const float* __restrict__ w_r_ylm_p,
    const float* __restrict__ w_r_yfm_p,
    const float* __restrict__ w_r_yvm_p,
    const float* __restrict__ b0_yom_p,
    const float* __restrict__ b1_yom_p,
    const float* __restrict__ b2_yom_p,
    const float* __restrict__ b0_ylm_p,
    const float* __restrict__ b1_ylm_p,
    const float* __restrict__ b2_ylm_p,
    const float* __restrict__ w_s_yvm_p,
    const float* __restrict__ b0_yrm_p,
    float* __restrict__ out)
{
    __shared__ float s_u1[8 * NCP];
    __shared__ float s_u2[8 * NCP];
    __shared__ float s_ag[8 * NCP];
    __shared__ float s_c [8 * NCP];
    __shared__ float redS[7];
    __shared__ float redQ[7];

    const int tid = threadIdx.x;
    const int wid = tid >> 5;
    const int lid = tid & 31;
    const int bstart = blockIdx.x * SLICE;

    const float mo = *p_mean_p;
    const float so = *p_std_p;
    int time_lag = *time_lag_p;
    if (time_lag < 0)  time_lag = 0;
    if (time_lag > NB) time_lag = NB;

    // ---- derived constants (all threads; needed by scan and expand)
    const float inv_so = __fdividef(1.0f, so);
    const float Bl = (*b1_ylm_p) * inv_so;
    const float Kl = (*b0_ylm_p) - mo * Bl;
    const float b2l_over_SL = (*b2_ylm_p) * (1.0f / 1.898f);

    const float eo    = __expf(*w_r_yom_p);
    const float el    = __expf(*w_r_ylm_p);
    const float ef    = __expf(*w_r_yfm_p);
    const float denom = eo + el + ef;
    const float co    = __fdividef(eo, denom);
    const float cl    = __fdividef(el, denom);

    const float Bo  = (*b1_yom_p) * inv_so;
    const float Ko  = (*b0_yom_p) - mo * Bo - mo * inv_so * (*b2_yom_p);
    const float Bo2 = -L2E * Bo;
    const float Ko2 = -L2E * Ko;
    const float Bl2 = -L2E * Bl;

    const float sv  = fsig(*w_r_yvm_p);
    const float es  = __expf(*w_s_yvm_p);
    const float ebr = __expf(*b0_yrm_p);
    const float thresh = ebr * 500.0f;
    const float Ct  = es * (1.0f / 500.0f);
    const float Dt  = ebr * es;
    const float Ct2 = es * (2.0f / 500.0f);
    const float Dt2 = 2.0f * ebr * es;
    const float sv2 = 2.0f * sv;

    // ---- stage the window (268 elements; zeros for global index < 0)
    const float2* x2 = (const float2*)x;
    for (int e = tid; e < NE; e += TPB) {
        int gi = bstart - W + e;
        float2 v = (gi >= 0) ? x2[gi] : make_float2(0.0f, 0.0f);
        int a = (e & 7) * NCP + (e >> 3);
        s_u1[a] = v.x;
        s_u2[a] = v.y;
        s_ag[a] = -L2E * (Kl + (v.y - 2.9086f) * b2l_over_SL);
    }
    __syncthreads();

    if (tid < NCH) {
        // ---- windowed scan: lane k covers chunk k with W-step warmup
        const int k   = tid;
        const int gi0 = bstart + k * CH - W;   // window start (global)
        float c = 0.0f;

        #pragma unroll
        for (int t = 0; t < W + CH; ++t) {
            const int l = k * CH + t;
            const int a = (l & 7) * NCP + (l >> 3);
            float u2 = s_u2[a];
            float ag = s_ag[a];

            float exo = ex2f(fmaf(c, Bo2, Ko2));        // e^{-xo}
            float exl = ex2f(fmaf(c, Bl2, ag));         // e^{-xl}
            float rc  = __fdividef(u2, c);
            float th  = tanh_approx(fmaf(c, Ct, -Dt));

            float oo  = co * __fdividef(1.0f, 1.0f + exo);
            float ol  = cl * __fdividef(1.0f, 1.0f + exl);
            float olc = (c > 0.0f) ? fminf(ol, rc) : ol;
            float f   = 1.0f - (oo + olc);
            float ov  = fminf(sv * th, f);
            float mr  = ov * fabsf(c - thresh);
            float c1  = fmaf(f, c, s_u1[a]) - mr;

            if (t >= W) s_c[a] = c;              // pre-update carry
            if (gi0 + t >= time_lag) c = c1;     // masked prefix: no update
        }
    } else {
        // ---- obs_std partials (warps 1-7), FP32
        float s = 0.0f, q = 0.0f;
        for (int i = SPIN + (tid - 32); i < TRAIN; i += TPB - 32) {
            float v = y_obs[i];
            s += v;
            q = fmaf(v, v, q);
        }
        #pragma unroll
        for (int off = 16; off > 0; off >>= 1) {
            s += __shfl_down_sync(0xFFFFFFFFu, s, off);
            q += __shfl_down_sync(0xFFFFFFFFu, q, off);
        }
        if (lid == 0) { redS[wid - 1] = s; redQ[wid - 1] = q; }
    }
    __syncthreads();

    // ---- obs_std finish (every thread; deterministic identical value)
    float S = 0.0f, Q = 0.0f;
    #pragma unroll
    for (int w = 0; w < 7; ++w) { S += redS[w]; Q += redQ[w]; }
    const float nn = (float)NSTD;
    const float obsstd = sqrtf((Q - __fdividef(S * S, nn)) *
                               __fdividef(1.0f, nn - 1.0f));

    // ---- expand: one output element per thread
    const int i = bstart + tid;

    if (i < time_lag) {
        out[0 * NB + i] = 0.0f;
        out[1 * NB + i] = 0.0f;
        out[2 * NB + i] = 0.0f;
        out[3 * NB + i] = 0.0f;
        out[4 * NB + i] = 0.0f;
        out[5 * NB + i] = 0.0f;
        out[6 * NB + i] = 0.0f;
        out[7 * NB + i] = 0.0f;
        out[8 * NB + i] = 0.0f;
        out[9 * NB + i] = 0.0f;
        out[10 * NB + 2 * i]     = 0.0f;
        out[10 * NB + 2 * i + 1] = 0.0f;
        out[12 * NB + i] = 0.0f;
        out[13 * NB + i] = 0.0f;
        out[14 * NB + i] = 0.0f;
        return;
    }

    const int e = tid + W;                       // local element of i
    const int a = (e & 7) * NCP + (e >> 3);      // <=2-way conflict, one-shot
    const float c  = s_c[a];
    const float u2 = s_u2[a];
    const float argl = Kl + (u2 - 2.9086f) * b2l_over_SL;

    float oo  = co * fsig(fmaf(c, Bo, Ko));
    float ol  = cl * fsig(fmaf(c, Bl, argl));
    float rc  = __fdividef(u2, c);
    float olc = (c > 0.0f) ? fminf(ol, rc) : ol;
    float f   = (1.0f - oo) - olc;
    float e2t = __expf(fmaf(c, Ct2, -Dt2));
    float ov1 = sv - __fdividef(sv2, e2t + 1.0f);   // sv * tanh (accurate)
    float ov  = fminf(ov1, f);
    float mr  = ov * fabsf(c - thresh);
    float h   = oo * c;

    out[0 * NB + i] = h;           // h_n
    out[1 * NB + i] = c;           // c_n
    out[2 * NB + i] = ol * c;      // l_n
    out[3 * NB + i] = olc * c;     // lc_n
    out[4 * NB + i] = 0.0f;        // bp_n
    out[5 * NB + i] = 0.0f;        // Gate_ib
    out[6 * NB + i] = oo;          // Gate_oo
    out[7 * NB + i] = ol;          // Gate_ol
    out[8 * NB + i] = olc;         // Gate_olc
    out[9 * NB + i] = f;           // Gate_f
    out[10 * NB + 2 * i]     = h;        // h_nout[:,0]
    out[10 * NB + 2 * i + 1] = obsstd;   // h_nout[:,1]
    out[12 * NB + i] = obsstd;     // obs_std
    out[13 * NB + i] = ov;         // Gate_ov
    out[14 * NB + i] = mr;         // mr_n
}

extern "C" void kernel_launch(void* const* d_in, const int* in_sizes, int n_in,
                              void* d_out, int out_size)
{
    const float* x        = (const float*)d_in[0];
    const float* y_obs    = (const float*)d_in[1];
    const float* p_mean   = (const float*)d_in[2];
    const float* p_std    = (const float*)d_in[3];
    const int*   time_lag = (const int*)  d_in[5];
    const float* w_r_yom  = (const float*)d_in[6];
    const float* w_r_ylm  = (const float*)d_in[7];
    const float* w_r_yfm  = (const float*)d_in[8];
    const float* w_r_yvm  = (const float*)d_in[9];
    const float* b0_yom   = (const float*)d_in[10];
    const float* b1_yom   = (const float*)d_in[11];
    const float* b2_yom   = (const float*)d_in[12];
    const float* b0_ylm   = (const float*)d_in[13];
    const float* b1_ylm   = (const float*)d_in[14];
    const float* b2_ylm   = (const float*)d_in[15];
    const float* w_s_yvm  = (const float*)d_in[16];
    const float* b0_yrm   = (const float*)d_in[17];

    float* out = (float*)d_out;

    mcp_win<<<NBLK, TPB>>>(
        x, y_obs, p_mean, p_std, time_lag,
        w_r_yom, w_r_ylm, w_r_yfm, w_r_yvm,
        b0_yom, b1_yom, b2_yom,
        b0_ylm, b1_ylm, b2_ylm,
        w_s_yvm, b0_yrm, out);
}